// round 7
// baseline (speedup 1.0000x reference)
#include <cuda_runtime.h>
#include <cstdint>

// AttentionLayer: B=2048, N=64, D=256, H=16
//   m_i[h]  = sum_d members[b,i,d]*item[b,d]*W1[d,h]
//   s[h]    = sum_i m_i[h] ; pre = 64*m_i - s + b1 ; relu ; logit = relu@W2 + b2
//   out[b,i] = softmax_i(logit)
//
// R7: block = 64 threads = 2 warps = 1 batch; warps split the D dimension
// (warp p owns d in [128p,128p+128), all 16 heads) -> zero duplication of
// gmem/STS/LDS traffic, zero block barriers in the main loop. Lane owns
// 4 heads (hg=lane&3) x 16 d (ds=lane>>2). m/s are per-warp partials reduced
// once in smem at the epilogue.

constexpr int Bb = 2048;
constexpr int Nn = 64;
constexpr int Dd = 256;
constexpr int Hh = 16;
constexpr int THREADS = 64;
constexpr int RING = 4;                // slots of 2 half-rows (1 KB) per warp
constexpr int MSTR = 18;               // mPart row stride (72B, 8B-aligned)

#define FMA2(acc, a, w)  asm("fma.rn.f32x2 %0, %1, %2, %0;" : "+l"(acc) : "l"(a), "l"(w))
#define ADD2(d, a, b_)   asm("add.rn.f32x2 %0, %1, %2;" : "=l"(d) : "l"(a), "l"(b_))
#define PACK2(d, lo, hi) asm("mov.b64 %0, {%1, %2};" : "=l"(d) : "f"(lo), "f"(hi))
#define UNPACK2(lo, hi, v) asm("mov.b64 {%0, %1}, %2;" : "=f"(lo), "=f"(hi) : "l"(v))

__device__ __forceinline__ uint32_t smem_u32(const void* p) {
    uint32_t a;
    asm("{ .reg .u64 t; cvta.to.shared.u64 t, %1; cvt.u32.u64 %0, t; }"
        : "=r"(a) : "l"(p));
    return a;
}
__device__ __forceinline__ void cp_async16(uint32_t dst, const void* src) {
    asm volatile("cp.async.cg.shared.global [%0], [%1], 16;" :: "r"(dst), "l"(src));
}
__device__ __forceinline__ void cp_commit() {
    asm volatile("cp.async.commit_group;" ::: "memory");
}
__device__ __forceinline__ void cp_wait2() {
    asm volatile("cp.async.wait_group %0;" :: "n"(RING - 2) : "memory");
}

__global__ __launch_bounds__(THREADS, 8)
void attn_kernel(const float* __restrict__ members,
                 const float* __restrict__ item,
                 const float* __restrict__ W1,
                 const float* __restrict__ b1,
                 const float* __restrict__ W2,
                 const float* __restrict__ b2,
                 float* __restrict__ out)
{
    __shared__ float4 ring[2][RING][2][32];    // [warp][slot][row][512B] = 8 KB
    __shared__ float  mPart[2][Nn][MSTR];      // 9.2 KB per-warp m partials
    __shared__ float  sPart[2][Hh];
    __shared__ float  red[2][2];               // [max|sum][warp]

    const int tid  = threadIdx.x;
    const int p    = tid >> 5;                 // warp: d in [128p, 128p+128)
    const int lane = tid & 31;
    const int hg   = lane & 3;                 // head group -> heads 4hg..4hg+3
    const int ds   = lane >> 2;                // d-slice: 16 d at offset 16*ds
    const int h0   = 4 * hg;
    const int b    = blockIdx.x;

    // warp's half-row base in gmem (float units)
    const float* gbase = members + (size_t)b * Nn * Dd + 128 * p;
    const uint32_t ringBase = smem_u32(&ring[p][0][0][0]);

    // ---- prologue: slots 0..2 (rows 0..5, this warp's halves) in flight ----
    #pragma unroll
    for (int it = 0; it < RING - 1; it++) {
        cp_async16(ringBase + it * 1024 +       lane * 16, gbase + (2 * it)     * Dd + lane * 4);
        cp_async16(ringBase + it * 1024 + 512 + lane * 16, gbase + (2 * it + 1) * Dd + lane * 4);
        cp_commit();
    }

    // ---- register weights: lane's 4 heads x 16 d (8 d-pairs) ----
    // wreg[4*pr + j] = (W1[d0][h0+j]*it[d0], W1[d0+1][h0+j]*it[d0+1]), d0 = base+2pr
    const float* itG = item + (size_t)b * Dd + 128 * p;
    const int dl = 16 * ds;                    // lane d-offset within the half
    unsigned long long wreg[32];
    #pragma unroll
    for (int pr = 0; pr < 8; pr++) {
        const int d0 = dl + 2 * pr;
        const float i0 = __ldg(&itG[d0]);
        const float i1 = __ldg(&itG[d0 + 1]);
        const float4 wA = __ldg((const float4*)&W1[(128 * p + d0)     * Hh + h0]);
        const float4 wB = __ldg((const float4*)&W1[(128 * p + d0 + 1) * Hh + h0]);
        PACK2(wreg[4 * pr + 0], wA.x * i0, wB.x * i1);
        PACK2(wreg[4 * pr + 1], wA.y * i0, wB.y * i1);
        PACK2(wreg[4 * pr + 2], wA.z * i0, wB.z * i1);
        PACK2(wreg[4 * pr + 3], wA.w * i0, wB.w * i1);
    }

    // ---- main loop: 32 iterations x 2 rows, no block barriers ----
    unsigned long long sAcc[4] = {0ull, 0ull, 0ull, 0ull};   // per-head e/o partials
    for (int i = 0; i < Nn / 2; i++) {
        cp_wait2();                 // this lane's groups for slot i complete
        __syncwarp();               // all lanes' fills of slot i visible

        if (i + RING - 1 < Nn / 2) {       // refill slot i+3 (buffer free)
            const int it = i + RING - 1;
            const uint32_t d0 = ringBase + (it & (RING - 1)) * 1024 + lane * 16;
            cp_async16(d0,       gbase + (2 * it)     * Dd + lane * 4);
            cp_async16(d0 + 512, gbase + (2 * it + 1) * Dd + lane * 4);
        }
        cp_commit();                // unconditional: wait arithmetic stays exact

        const unsigned long long* slot =
            (const unsigned long long*)&ring[p][i & (RING - 1)][0][0];

        #pragma unroll
        for (int rr = 0; rr < 2; rr++) {
            const ulonglong2* rp = (const ulonglong2*)(slot + rr * 64 + ds * 8);
            const ulonglong2 u0 = rp[0];   // 4 LDS.128: lane's 64B slice
            const ulonglong2 u1 = rp[1];   // 8 distinct addrs/warp, 4-way bcast
            const ulonglong2 u2 = rp[2];
            const ulonglong2 u3 = rp[3];
            const unsigned long long u[8] =
                {u0.x, u0.y, u1.x, u1.y, u2.x, u2.y, u3.x, u3.y};

            unsigned long long acc[4] = {0ull, 0ull, 0ull, 0ull};
            #pragma unroll
            for (int pr = 0; pr < 8; pr++) {
                FMA2(acc[0], u[pr], wreg[4 * pr + 0]);
                FMA2(acc[1], u[pr], wreg[4 * pr + 1]);
                FMA2(acc[2], u[pr], wreg[4 * pr + 2]);
                FMA2(acc[3], u[pr], wreg[4 * pr + 3]);
            }
            ADD2(sAcc[0], sAcc[0], acc[0]);
            ADD2(sAcc[1], sAcc[1], acc[1]);
            ADD2(sAcc[2], sAcc[2], acc[2]);
            ADD2(sAcc[3], sAcc[3], acc[3]);

            float x, y, m0, m1, m2, m3;
            UNPACK2(x, y, acc[0]); m0 = x + y;
            UNPACK2(x, y, acc[1]); m1 = x + y;
            UNPACK2(x, y, acc[2]); m2 = x + y;
            UNPACK2(x, y, acc[3]); m3 = x + y;
            unsigned long long mm0, mm1, tmp;
            PACK2(mm0, m0, m1);
            PACK2(mm1, m2, m3);
            #pragma unroll
            for (int o = 4; o <= 16; o <<= 1) {   // reduce over the 8 ds lanes
                tmp = __shfl_xor_sync(0xffffffffu, mm0, o); ADD2(mm0, mm0, tmp);
                tmp = __shfl_xor_sync(0xffffffffu, mm1, o); ADD2(mm1, mm1, tmp);
            }
            if (lane < 4) {                      // ds==0 lanes publish 4 heads
                const int r = 2 * i + rr;
                *(unsigned long long*)&mPart[p][r][h0]     = mm0;
                *(unsigned long long*)&mPart[p][r][h0 + 2] = mm1;
            }
        }
    }

    // ---- publish this warp's s partials ----
    {
        float x, y, s0, s1, s2, s3;
        UNPACK2(x, y, sAcc[0]); s0 = x + y;
        UNPACK2(x, y, sAcc[1]); s1 = x + y;
        UNPACK2(x, y, sAcc[2]); s2 = x + y;
        UNPACK2(x, y, sAcc[3]); s3 = x + y;
        unsigned long long ss0, ss1, tmp;
        PACK2(ss0, s0, s1);
        PACK2(ss1, s2, s3);
        #pragma unroll
        for (int o = 4; o <= 16; o <<= 1) {
            tmp = __shfl_xor_sync(0xffffffffu, ss0, o); ADD2(ss0, ss0, tmp);
            tmp = __shfl_xor_sync(0xffffffffu, ss1, o); ADD2(ss1, ss1, tmp);
        }
        if (lane < 4) {
            *(unsigned long long*)&sPart[p][h0]     = ss0;
            *(unsigned long long*)&sPart[p][h0 + 2] = ss1;
        }
    }
    __syncthreads();                // barrier #1: partials complete

    // ---- epilogue: row = tid; combine warp partials, MLP, softmax ----
    const int row = tid;
    float logit = __ldg(b2);
    #pragma unroll
    for (int hh = 0; hh < 16; hh++) {
        const float m = mPart[0][row][hh] + mPart[1][row][hh];
        const float s = sPart[0][hh] + sPart[1][hh];
        const float pre = 64.f * m + __ldg(&b1[hh]) - s;
        logit += fmaxf(pre, 0.f) * __ldg(&W2[hh]);
    }

    float mx = logit;
    #pragma unroll
    for (int o = 16; o >= 1; o >>= 1)
        mx = fmaxf(mx, __shfl_xor_sync(0xffffffffu, mx, o));
    if (lane == 0) red[0][p] = mx;
    __syncthreads();                // barrier #2
    const float mxAll = fmaxf(red[0][0], red[0][1]);

    const float e = __expf(logit - mxAll);
    float sm = e;
    #pragma unroll
    for (int o = 16; o >= 1; o >>= 1)
        sm += __shfl_xor_sync(0xffffffffu, sm, o);
    if (lane == 0) red[1][p] = sm;
    __syncthreads();                // barrier #3
    const float inv = 1.0f / (red[1][0] + red[1][1]);

    out[(size_t)b * Nn + row] = e * inv;
}

extern "C" void kernel_launch(void* const* d_in, const int* in_sizes, int n_in,
                              void* d_out, int out_size)
{
    attn_kernel<<<Bb, THREADS>>>(
        (const float*)d_in[0],   // members_embeds [2048,64,256]
        (const float*)d_in[1],   // item_embeds    [2048,256]
        (const float*)d_in[2],   // W1 [256,16]
        (const float*)d_in[3],   // b1 [16]
        (const float*)d_in[4],   // W2 [16,1]
        (const float*)d_in[5],   // b2 [1]
        (float*)d_out);          // out [2048,64]
}

// round 8
// speedup vs baseline: 1.5863x; 1.5863x over previous
#include <cuda_runtime.h>
#include <cstdint>

// AttentionLayer: B=2048, N=64, D=256, H=16
//   m_i[h]  = sum_d members[b,i,d]*item[b,d]*W1[d,h]
//   s[h]    = sum_i m_i[h] ; pre = 64*m_i - s + b1 ; relu ; logit = relu@W2 + b2
//   out[b,i] = softmax_i(logit)
//
// R8: block = 64 threads = 2 warps = 1 batch (grid 2048). Head-split: warp p
// owns heads 8p..8p+7; lane owns 2 heads (hgrp=lane&3 -> h0=8p+2*hgrp) x
// 32 d (quads 8t + ds, ds=lane>>2). Private per-warp cp.async ring of
// 2 slots x 4 rows -> ONE wait + ONE commit per 4 rows, no block barriers,
// 4 independent butterfly chains per iteration (shfl latency hidden by ILP).

constexpr int Bb = 2048;
constexpr int Nn = 64;
constexpr int Dd = 256;
constexpr int Hh = 16;
constexpr int THREADS = 64;
constexpr int RING = 2;                // slots of 4 rows (4 KB) per warp
constexpr int ITERS = Nn / 4;          // 16 iterations x 4 rows
constexpr int MSTR = 18;               // mS row stride (72 B, 8B-aligned)

#define FMA2(acc, a, w)  asm("fma.rn.f32x2 %0, %1, %2, %0;" : "+l"(acc) : "l"(a), "l"(w))
#define ADD2(d, a, b_)   asm("add.rn.f32x2 %0, %1, %2;" : "=l"(d) : "l"(a), "l"(b_))
#define PACK2(d, lo, hi) asm("mov.b64 %0, {%1, %2};" : "=l"(d) : "f"(lo), "f"(hi))
#define UNPACK2(lo, hi, v) asm("mov.b64 {%0, %1}, %2;" : "=f"(lo), "=f"(hi) : "l"(v))

__device__ __forceinline__ uint32_t smem_u32(const void* p) {
    uint32_t a;
    asm("{ .reg .u64 t; cvta.to.shared.u64 t, %1; cvt.u32.u64 %0, t; }"
        : "=r"(a) : "l"(p));
    return a;
}
__device__ __forceinline__ void cp_async16(uint32_t dst, const void* src) {
    asm volatile("cp.async.cg.shared.global [%0], [%1], 16;" :: "r"(dst), "l"(src));
}
__device__ __forceinline__ void cp_commit() {
    asm volatile("cp.async.commit_group;" ::: "memory");
}
__device__ __forceinline__ void cp_wait1() {
    asm volatile("cp.async.wait_group 1;" ::: "memory");
}

__global__ __launch_bounds__(THREADS, 8)
void attn_kernel(const float* __restrict__ members,
                 const float* __restrict__ item,
                 const float* __restrict__ W1,
                 const float* __restrict__ b1,
                 const float* __restrict__ W2,
                 const float* __restrict__ b2,
                 float* __restrict__ out)
{
    __shared__ float4 ring[2][RING][4][Dd / 4];   // [warp][slot][row] = 16 KB
    __shared__ float  mS[Nn * MSTR];              // 4.6 KB (warps write disjoint heads)
    __shared__ float  sS[Hh];
    __shared__ float  red[2][2];                  // [max|sum][warp]

    const int tid  = threadIdx.x;
    const int p    = tid >> 5;                 // warp: heads 8p..8p+7
    const int lane = tid & 31;
    const int hgrp = lane & 3;                 // head pair within warp
    const int ds   = lane >> 2;                // d-eighth (quads 8t + ds)
    const int h0   = 8 * p + 2 * hgrp;         // lane's first head
    const int b    = blockIdx.x;

    const float4* grow = (const float4*)(members + (size_t)b * Nn * Dd);
    const uint32_t ringBase = smem_u32(&ring[p][0][0][0]);

    // ---- prologue: both slots (rows 0..7) in flight ----
    #pragma unroll
    for (int s = 0; s < RING; s++) {
        #pragma unroll
        for (int rr = 0; rr < 4; rr++) {
            const uint32_t d0 = ringBase + s * 4096 + rr * 1024 + lane * 16;
            const float4* g = grow + (4 * s + rr) * 64;
            cp_async16(d0,       g + lane);
            cp_async16(d0 + 512, g + lane + 32);
        }
        cp_commit();
    }

    // ---- register weights: lane's 2 heads x 32 d (R5 layout) ----
    // wreg[4t+2j+par] = packed (W1[d,h0+j]*it[d]) for quad 8t+ds, pair par
    const float* itG = item + (size_t)b * Dd;
    unsigned long long wreg[32];
    #pragma unroll
    for (int t = 0; t < 8; t++) {
        const int d0 = (8 * t + ds) * 4;
        const float4 it4 = __ldg((const float4*)&itG[d0]);
        #pragma unroll
        for (int j = 0; j < 2; j++) {
            const int h = h0 + j;
            float w0 = __ldg(&W1[(d0 + 0) * Hh + h]) * it4.x;
            float w1 = __ldg(&W1[(d0 + 1) * Hh + h]) * it4.y;
            float w2 = __ldg(&W1[(d0 + 2) * Hh + h]) * it4.z;
            float w3 = __ldg(&W1[(d0 + 3) * Hh + h]) * it4.w;
            PACK2(wreg[4 * t + 2 * j],     w0, w1);
            PACK2(wreg[4 * t + 2 * j + 1], w2, w3);
        }
    }

    // ---- main loop: 16 iterations x 4 rows, no block barriers ----
    unsigned long long sAcc = 0ull;            // packed (s_h0, s_h1), post-reduce
    for (int i = 0; i < ITERS; i++) {
        cp_wait1();                 // slot i&1 landed (1 newer group pending)
        __syncwarp();               // all lanes' fills of this slot visible

        const int s = i & 1;
        unsigned long long mm[4];
        #pragma unroll
        for (int rr = 0; rr < 4; rr++) {
            const ulonglong2* rp = (const ulonglong2*)&ring[p][s][rr][0];
            unsigned long long a0 = 0ull, a1 = 0ull, a2 = 0ull, a3 = 0ull;
            #pragma unroll
            for (int t = 0; t < 8; t++) {
                const ulonglong2 u = rp[8 * t + ds];   // 128B contig, 4-way bcast
                FMA2(a0, u.x, wreg[4 * t + 0]);
                FMA2(a1, u.y, wreg[4 * t + 1]);
                FMA2(a2, u.x, wreg[4 * t + 2]);
                FMA2(a3, u.y, wreg[4 * t + 3]);
            }
            ADD2(a0, a0, a1);       // head0 (even,odd pairs folded)
            ADD2(a2, a2, a3);       // head1
            float x, y, m0, m1;
            UNPACK2(x, y, a0); m0 = x + y;
            UNPACK2(x, y, a2); m1 = x + y;
            PACK2(mm[rr], m0, m1);  // (m_h0, m_h1) for row 4i+rr
        }

        // 4 independent 3-level butterflies over the 8 ds lanes (xor 4,8,16)
        unsigned long long tmp;
        #pragma unroll
        for (int o = 4; o <= 16; o <<= 1) {
            tmp = __shfl_xor_sync(0xffffffffu, mm[0], o); ADD2(mm[0], mm[0], tmp);
            tmp = __shfl_xor_sync(0xffffffffu, mm[1], o); ADD2(mm[1], mm[1], tmp);
            tmp = __shfl_xor_sync(0xffffffffu, mm[2], o); ADD2(mm[2], mm[2], tmp);
            tmp = __shfl_xor_sync(0xffffffffu, mm[3], o); ADD2(mm[3], mm[3], tmp);
        }
        ADD2(sAcc, sAcc, mm[0]);
        ADD2(sAcc, sAcc, mm[1]);
        ADD2(sAcc, sAcc, mm[2]);
        ADD2(sAcc, sAcc, mm[3]);

        if (lane < 4) {             // ds==0 lanes publish their 2 heads x 4 rows
            #pragma unroll
            for (int rr = 0; rr < 4; rr++)
                *(unsigned long long*)&mS[(4 * i + rr) * MSTR + h0] = mm[rr];
        }

        __syncwarp();               // reads of slot s done before refilling it
        if (i + RING < ITERS) {     // refill this slot with iteration i+2
            const int it = i + RING;
            #pragma unroll
            for (int rr = 0; rr < 4; rr++) {
                const uint32_t d0 = ringBase + s * 4096 + rr * 1024 + lane * 16;
                const float4* g = grow + (4 * it + rr) * 64;
                cp_async16(d0,       g + lane);
                cp_async16(d0 + 512, g + lane + 32);
            }
        }
        cp_commit();                // unconditional: wait arithmetic stays exact
    }

    // sAcc already fully reduced across lanes; lanes 0-3 publish 2 heads each
    if (lane < 4) *(unsigned long long*)&sS[h0] = sAcc;
    __syncthreads();                // barrier #1: mS + sS complete

    // ---- epilogue: row = tid ----
    const int row = tid;
    float logit = __ldg(b2);
    #pragma unroll
    for (int hh = 0; hh < 16; hh++) {
        const float pre = 64.f * mS[row * MSTR + hh] + __ldg(&b1[hh]) - sS[hh];
        logit += fmaxf(pre, 0.f) * __ldg(&W2[hh]);
    }

    float mx = logit;
    #pragma unroll
    for (int o = 16; o >= 1; o >>= 1)
        mx = fmaxf(mx, __shfl_xor_sync(0xffffffffu, mx, o));
    if (lane == 0) red[0][p] = mx;
    __syncthreads();                // barrier #2
    const float mxAll = fmaxf(red[0][0], red[0][1]);

    const float e = __expf(logit - mxAll);
    float sm = e;
    #pragma unroll
    for (int o = 16; o >= 1; o >>= 1)
        sm += __shfl_xor_sync(0xffffffffu, sm, o);
    if (lane == 0) red[1][p] = sm;
    __syncthreads();                // barrier #3
    const float inv = 1.0f / (red[1][0] + red[1][1]);

    out[(size_t)b * Nn + row] = e * inv;
}

extern "C" void kernel_launch(void* const* d_in, const int* in_sizes, int n_in,
                              void* d_out, int out_size)
{
    attn_kernel<<<Bb, THREADS>>>(
        (const float*)d_in[0],   // members_embeds [2048,64,256]
        (const float*)d_in[1],   // item_embeds    [2048,256]
        (const float*)d_in[2],   // W1 [256,16]
        (const float*)d_in[3],   // b1 [16]
        (const float*)d_in[4],   // W2 [16,1]
        (const float*)d_in[5],   // b2 [1]
        (float*)d_out);          // out [2048,64]
}